// round 1
// baseline (speedup 1.0000x reference)
#include <cuda_runtime.h>
#include <math.h>

#define NROWS 16384
#define DCOLS 4096
#define TPB   256
#define NWARP (TPB / 32)

__device__ float g_partials[NROWS];

__global__ __launch_bounds__(TPB, 8)
void nce_row_kernel(const float* __restrict__ labels,
                    const float* __restrict__ logits,
                    const float* __restrict__ alpha)
{
    __shared__ float srow[DCOLS];          // 16 KB: staged logits row
    __shared__ float s_max[NWARP];
    __shared__ float s_lv[NWARP];
    __shared__ int   s_li[NWARP];
    __shared__ float s_sum[NWARP];
    __shared__ float s_bm;                  // block row-max of logits
    __shared__ int   s_bpos;                // block argmax index of labels
    __shared__ float s_bsum;                // block sum of exp

    const int row = blockIdx.x;
    const int tid = threadIdx.x;
    const int lane = tid & 31;
    const int wid  = tid >> 5;

    const float4* lg4 = reinterpret_cast<const float4*>(logits + (size_t)row * DCOLS);
    const float4* lb4 = reinterpret_cast<const float4*>(labels + (size_t)row * DCOLS);
    float4* sr4 = reinterpret_cast<float4*>(srow);

    float lmax = -INFINITY;          // max of logits row
    float labv = -INFINITY;          // max of labels row
    int   labi = 0;                  // its index

    // Pass 1: stream logits -> smem (tracking max), labels -> argmax. 512 B/thread.
    #pragma unroll
    for (int it = 0; it < DCOLS / 4 / TPB; it++) {
        const int idx = it * TPB + tid;
        float4 v = lg4[idx];
        float4 b = lb4[idx];
        sr4[idx] = v;
        lmax = fmaxf(lmax, fmaxf(fmaxf(v.x, v.y), fmaxf(v.z, v.w)));
        const int base = idx * 4;
        if (b.x > labv) { labv = b.x; labi = base; }
        if (b.y > labv) { labv = b.y; labi = base + 1; }
        if (b.z > labv) { labv = b.z; labi = base + 2; }
        if (b.w > labv) { labv = b.w; labi = base + 3; }
    }

    // Warp reduce: max(logits), argmax(labels) with first-occurrence tie-break.
    #pragma unroll
    for (int off = 16; off > 0; off >>= 1) {
        float om = __shfl_down_sync(0xffffffffu, lmax, off);
        float ov = __shfl_down_sync(0xffffffffu, labv, off);
        int   oi = __shfl_down_sync(0xffffffffu, labi, off);
        lmax = fmaxf(lmax, om);
        if (ov > labv || (ov == labv && oi < labi)) { labv = ov; labi = oi; }
    }
    if (lane == 0) { s_max[wid] = lmax; s_lv[wid] = labv; s_li[wid] = labi; }
    __syncthreads();   // also covers srow stores

    if (wid == 0) {
        float m = (lane < NWARP) ? s_max[lane] : -INFINITY;
        float v = (lane < NWARP) ? s_lv[lane]  : -INFINITY;
        int   i = (lane < NWARP) ? s_li[lane]  : 0;
        #pragma unroll
        for (int off = NWARP / 2; off > 0; off >>= 1) {
            float om = __shfl_down_sync(0xffffffffu, m, off);
            float ov = __shfl_down_sync(0xffffffffu, v, off);
            int   oi = __shfl_down_sync(0xffffffffu, i, off);
            m = fmaxf(m, om);
            if (ov > v || (ov == v && oi < i)) { v = ov; i = oi; }
        }
        if (lane == 0) { s_bm = m; s_bpos = i; }
    }
    __syncthreads();

    const float m = s_bm;
    const int pos = s_bpos;
    const float inv_alpha = 1.0f / alpha[0];
    const float c = inv_alpha * 1.4426950408889634f;   // 1/alpha * log2(e)

    // Pass 2: sum of exp((x - m)/alpha) from smem via exp2.
    float acc = 0.0f;
    #pragma unroll
    for (int it = 0; it < DCOLS / 4 / TPB; it++) {
        float4 v = sr4[it * TPB + tid];
        acc += exp2f((v.x - m) * c);
        acc += exp2f((v.y - m) * c);
        acc += exp2f((v.z - m) * c);
        acc += exp2f((v.w - m) * c);
    }
    #pragma unroll
    for (int off = 16; off > 0; off >>= 1)
        acc += __shfl_down_sync(0xffffffffu, acc, off);
    if (lane == 0) s_sum[wid] = acc;
    __syncthreads();

    if (tid == 0) {
        float total = 0.0f;
        #pragma unroll
        for (int w = 0; w < NWARP; w++) total += s_sum[w];
        // logz - pos  =  m/alpha + ln(total) - logits[pos]/alpha
        g_partials[row] = (m - srow[pos]) * inv_alpha + logf(total);
    }
}

__global__ __launch_bounds__(1024)
void nce_final_kernel(float* __restrict__ out)
{
    __shared__ float s[32];
    const int tid = threadIdx.x;
    const int lane = tid & 31;
    const int wid  = tid >> 5;

    float acc = 0.0f;
    #pragma unroll
    for (int i = 0; i < NROWS / 1024; i++)
        acc += g_partials[i * 1024 + tid];

    #pragma unroll
    for (int off = 16; off > 0; off >>= 1)
        acc += __shfl_down_sync(0xffffffffu, acc, off);
    if (lane == 0) s[wid] = acc;
    __syncthreads();
    if (wid == 0) {
        float v = (lane < 32) ? s[lane] : 0.0f;
        #pragma unroll
        for (int off = 16; off > 0; off >>= 1)
            v += __shfl_down_sync(0xffffffffu, v, off);
        if (lane == 0) out[0] = v * (1.0f / (float)NROWS);
    }
}

extern "C" void kernel_launch(void* const* d_in, const int* in_sizes, int n_in,
                              void* d_out, int out_size)
{
    const float* labels = (const float*)d_in[0];
    const float* logits = (const float*)d_in[1];
    // d_in[2] = mask (unused by the reference math)
    const float* alpha  = (const float*)d_in[3];
    float* out = (float*)d_out;

    nce_row_kernel<<<NROWS, TPB>>>(labels, logits, alpha);
    nce_final_kernel<<<1, 1024>>>(out);
}

// round 2
// speedup vs baseline: 1.0072x; 1.0072x over previous
#include <cuda_runtime.h>
#include <math.h>

#define NROWS 16384
#define DCOLS 4096
#define TPB   256
#define NWARP (TPB / 32)
#define VPT   (DCOLS / 4 / TPB)   // float4 chunks per thread = 4

__global__ void nce_zero_kernel(float* __restrict__ out) { out[0] = 0.0f; }

// Merge two (max, sumexp) pairs for logsumexp. Assumes at least one m finite
// whenever the result is consumed.
__device__ __forceinline__ void lse_merge(float& m, float& a, float mo, float ao, float c)
{
    float nm = fmaxf(m, mo);
    a = a * exp2f((m - nm) * c) + ao * exp2f((mo - nm) * c);
    m = nm;
}

__global__ __launch_bounds__(TPB)
void nce_row_kernel(const float* __restrict__ labels,
                    const float* __restrict__ logits,
                    const float* __restrict__ alpha,
                    float* __restrict__ out)
{
    __shared__ float s_m[NWARP];
    __shared__ float s_a[NWARP];
    __shared__ float s_lv[NWARP];
    __shared__ int   s_li[NWARP];
    __shared__ float s_fm;   // block max of logits
    __shared__ float s_fa;   // block sumexp
    __shared__ int   s_fp;   // block argmax index of labels

    const int row  = blockIdx.x;
    const int tid  = threadIdx.x;
    const int lane = tid & 31;
    const int wid  = tid >> 5;

    const float4* __restrict__ lg4 =
        reinterpret_cast<const float4*>(logits + (size_t)row * DCOLS);
    const float4* __restrict__ lb4 =
        reinterpret_cast<const float4*>(labels + (size_t)row * DCOLS);

    // Front-batch ALL global loads (MLP = 8 per thread).
    float4 v[VPT], b[VPT];
    #pragma unroll
    for (int i = 0; i < VPT; i++) v[i] = lg4[i * TPB + tid];
    #pragma unroll
    for (int i = 0; i < VPT; i++) b[i] = lb4[i * TPB + tid];

    const float inv_alpha = 1.0f / alpha[0];
    const float c = inv_alpha * 1.4426950408889634f;   // log2(e)/alpha

    // Thread-local max of the 16 logits (all in registers).
    float m = -INFINITY;
    #pragma unroll
    for (int i = 0; i < VPT; i++)
        m = fmaxf(m, fmaxf(fmaxf(v[i].x, v[i].y), fmaxf(v[i].z, v[i].w)));

    // Thread-local sum of exp((x - m)/alpha).
    float a = 0.0f;
    #pragma unroll
    for (int i = 0; i < VPT; i++) {
        a += exp2f((v[i].x - m) * c);
        a += exp2f((v[i].y - m) * c);
        a += exp2f((v[i].z - m) * c);
        a += exp2f((v[i].w - m) * c);
    }

    // Thread-local argmax of labels (first occurrence).
    float lv = -INFINITY;
    int   li = 0;
    #pragma unroll
    for (int i = 0; i < VPT; i++) {
        const int base = (i * TPB + tid) * 4;
        if (b[i].x > lv) { lv = b[i].x; li = base; }
        if (b[i].y > lv) { lv = b[i].y; li = base + 1; }
        if (b[i].z > lv) { lv = b[i].z; li = base + 2; }
        if (b[i].w > lv) { lv = b[i].w; li = base + 3; }
    }

    // Warp reduce.
    #pragma unroll
    for (int off = 16; off > 0; off >>= 1) {
        float mo = __shfl_down_sync(0xffffffffu, m,  off);
        float ao = __shfl_down_sync(0xffffffffu, a,  off);
        float ov = __shfl_down_sync(0xffffffffu, lv, off);
        int   oi = __shfl_down_sync(0xffffffffu, li, off);
        lse_merge(m, a, mo, ao, c);
        if (ov > lv || (ov == lv && oi < li)) { lv = ov; li = oi; }
    }
    if (lane == 0) { s_m[wid] = m; s_a[wid] = a; s_lv[wid] = lv; s_li[wid] = li; }
    __syncthreads();

    // Cross-warp reduce in warp 0 (8 valid lanes).
    if (wid == 0) {
        m  = (lane < NWARP) ? s_m[lane]  : -INFINITY;
        a  = (lane < NWARP) ? s_a[lane]  : 0.0f;
        lv = (lane < NWARP) ? s_lv[lane] : -INFINITY;
        li = (lane < NWARP) ? s_li[lane] : 0x7fffffff;
        #pragma unroll
        for (int off = NWARP / 2; off > 0; off >>= 1) {
            float mo = __shfl_down_sync(0xffffffffu, m,  off);
            float ao = __shfl_down_sync(0xffffffffu, a,  off);
            float ov = __shfl_down_sync(0xffffffffu, lv, off);
            int   oi = __shfl_down_sync(0xffffffffu, li, off);
            lse_merge(m, a, mo, ao, c);
            if (ov > lv || (ov == lv && oi < li)) { lv = ov; li = oi; }
        }
        if (lane == 0) {
            // positive logit: re-read one element (L1/L2 hit — this CTA just read it)
            float posv = __ldg(logits + (size_t)row * DCOLS + li);
            float loss = (m - posv) * inv_alpha + logf(a);
            atomicAdd(out, loss * (1.0f / (float)NROWS));
        }
    }
}

extern "C" void kernel_launch(void* const* d_in, const int* in_sizes, int n_in,
                              void* d_out, int out_size)
{
    const float* labels = (const float*)d_in[0];
    const float* logits = (const float*)d_in[1];
    // d_in[2] = mask (unused by the reference math)
    const float* alpha  = (const float*)d_in[3];
    float* out = (float*)d_out;

    nce_zero_kernel<<<1, 1>>>(out);
    nce_row_kernel<<<NROWS, TPB>>>(labels, logits, alpha, out);
}